// round 8
// baseline (speedup 1.0000x reference)
#include <cuda_runtime.h>
#include <cuda_bf16.h>
#include <math.h>
#include <stdint.h>

#define NB   64
#define NPER 256
#define DIN  256
#define DOUT 128
#define EPER 8192
#define MAXE 192
#define ADJ_N 8192
#define ADJ_ELEMS (67108864u)
#define NROWS (NB*NPER)          // 16384

// ---------------- scratch ----------------
__device__ float g_T[NROWS*512];                // X @ Wcat  (cols: Wf_top|Wf_bot|Wp_top|Wp_bot)
__device__ float g_feat[NROWS*DOUT];
__device__ float g_assign[NROWS*DOUT];
__device__ float g_AS[NROWS*DOUT];
__device__ float g_ssq[4*NROWS];                // [which*2+fh][row] partial sum-of-squares
__device__ unsigned char g_elist[NROWS*MAXE];
__device__ int   g_ecnt[NROWS];
__device__ float g_ideg[NROWS];
// fragment-major bf16x2 words:
//   X:  [m_tile(1024)][k_chunk(16)][lane(32)][reg(4)]
//   WT: [n_tile(64)]  [k_chunk(16)][lane(32)][reg(2)]
__device__ unsigned int g_Xh[NROWS*128];
__device__ unsigned int g_Xl[NROWS*128];
__device__ unsigned int g_WTh[512*128];
__device__ unsigned int g_WTl[512*128];

// ---------------- f32x2 helpers ----------------
__device__ __forceinline__ unsigned long long fma2(unsigned long long a,
                                                   unsigned long long b,
                                                   unsigned long long c) {
    unsigned long long d;
    asm("fma.rn.f32x2 %0, %1, %2, %3;" : "=l"(d) : "l"(a), "l"(b), "l"(c));
    return d;
}
__device__ __forceinline__ unsigned long long add2(unsigned long long a,
                                                   unsigned long long b) {
    unsigned long long d;
    asm("add.rn.f32x2 %0, %1, %2;" : "=l"(d) : "l"(a), "l"(b));
    return d;
}
__device__ __forceinline__ unsigned long long dup2(float w) {
    unsigned long long d;
    asm("mov.b64 %0, {%1, %1};" : "=l"(d) : "f"(w));
    return d;
}
__device__ __forceinline__ void unpack2(unsigned long long v, float& lo, float& hi) {
    asm("mov.b64 {%0, %1}, %2;" : "=f"(lo), "=f"(hi) : "l"(v));
}

// ---------------- mma.sync bf16 (baseline PTX) ----------
__device__ __forceinline__ void mma16816(float* c, const uint32_t* a, const uint32_t* b) {
    asm volatile(
        "mma.sync.aligned.m16n8k16.row.col.f32.bf16.bf16.f32 "
        "{%0,%1,%2,%3}, {%4,%5,%6,%7}, {%8,%9}, {%0,%1,%2,%3};"
        : "+f"(c[0]), "+f"(c[1]), "+f"(c[2]), "+f"(c[3])
        : "r"(a[0]), "r"(a[1]), "r"(a[2]), "r"(a[3]), "r"(b[0]), "r"(b[1]));
}

// ---------------- K-build ----------------
__global__ void k_build(const int* __restrict__ esrc, const int* __restrict__ edst) {
    int b = blockIdx.x;
    __shared__ int scnt[NPER];
    for (int i = threadIdx.x; i < NPER; i += blockDim.x) scnt[i] = 0;
    __syncthreads();
    const int* s = esrc + b*EPER;
    const int* d = edst + b*EPER;
    for (int e = threadIdx.x; e < EPER; e += blockDim.x) {
        int dst = d[e];
        int src = s[e];
        int pos = atomicAdd(&scnt[dst], 1);
        if (pos < MAXE) g_elist[(b*NPER + dst)*MAXE + pos] = (unsigned char)src;
    }
    __syncthreads();
    for (int i = threadIdx.x; i < NPER; i += blockDim.x) {
        int c = scnt[i];
        g_ecnt[b*NPER + i] = c;
        g_ideg[b*NPER + i] = 1.0f / (float)(c > 0 ? c : 1);
    }
}

// ---------------- K-prep: bf16 hi/lo split into mma-fragment layout ------------
__device__ __forceinline__ void split2(float a, float b, unsigned int& hi, unsigned int& lo) {
    __nv_bfloat16 ah = __float2bfloat16(a);
    __nv_bfloat16 bh = __float2bfloat16(b);
    __nv_bfloat16 al = __float2bfloat16(a - __bfloat162float(ah));
    __nv_bfloat16 bl = __float2bfloat16(b - __bfloat162float(bh));
    __nv_bfloat162 hh; hh.x = ah; hh.y = bh;
    __nv_bfloat162 ll; ll.x = al; ll.y = bl;
    hi = *reinterpret_cast<unsigned int*>(&hh);
    lo = *reinterpret_cast<unsigned int*>(&ll);
}

__global__ void k_prep(const float* __restrict__ h,
                       const float* __restrict__ Wf, const float* __restrict__ Wp) {
    int idx = blockIdx.x*256 + threadIdx.x;
    if (blockIdx.x < 8192) {
        int reg = idx & 3, lane = (idx >> 2) & 31, kc = (idx >> 7) & 15, mt = idx >> 11;
        int g = lane >> 2, tg = lane & 3;
        int row = mt*16 + g + (reg & 1)*8;
        int w = tg + (reg >> 1)*4;
        const float* hp = h + (size_t)row*DIN + (kc*8 + w)*2;
        unsigned int hi, lo;
        split2(hp[0], hp[1], hi, lo);
        g_Xh[idx] = hi;
        g_Xl[idx] = lo;
    } else {
        int widx = idx - 8192*256;       // [0, 65536)
        int reg = widx & 1, lane = (widx >> 1) & 31, kc = (widx >> 6) & 15, nt = widx >> 10;
        int g = lane >> 2, tg = lane & 3;
        int n = nt*8 + g;
        int w = tg + reg*4;
        int k = (kc*8 + w)*2;
        int seg = n >> 7;
        const float* Wb = (seg < 2) ? Wf : Wp;
        int col = n & 127;
        int krow = k + ((seg & 1) ? 256 : 0);
        float x0 = Wb[(size_t)krow*128 + col];
        float x1 = Wb[(size_t)(krow+1)*128 + col];
        unsigned int hi, lo;
        split2(x0, x1, hi, lo);
        g_WTh[widx] = hi;
        g_WTl[widx] = lo;
    }
}

// ---------------- K-gemm (HMMA): T = X @ Wcat via 3-pass bf16 split ------------
__global__ void __launch_bounds__(256) k_gemm_mma() {
    int t = threadIdx.x, lane = t & 31, w = t >> 5;
    int wm = w & 1, wn = w >> 1;
    int mt0 = blockIdx.x*8 + wm*4;      // m-tile (16 rows each)
    int nt0 = blockIdx.y*16 + wn*4;     // n-tile (8 cols each)

    float acc[4][4][4];
    #pragma unroll
    for (int i = 0; i < 4; i++)
        #pragma unroll
        for (int j = 0; j < 4; j++)
            #pragma unroll
            for (int r = 0; r < 4; r++) acc[i][j][r] = 0.f;

    const uint4* Xh4 = (const uint4*)g_Xh;
    const uint4* Xl4 = (const uint4*)g_Xl;
    const uint2* Wh2 = (const uint2*)g_WTh;
    const uint2* Wl2 = (const uint2*)g_WTl;

    for (int kc = 0; kc < 16; kc++) {
        uint4 Ah[4], Al[4];
        uint2 Bh[4], Bl[4];
        #pragma unroll
        for (int i = 0; i < 4; i++) {
            int off = ((mt0 + i)*16 + kc)*32 + lane;
            Ah[i] = Xh4[off];
            Al[i] = Xl4[off];
        }
        #pragma unroll
        for (int j = 0; j < 4; j++) {
            int off = ((nt0 + j)*16 + kc)*32 + lane;
            Bh[j] = Wh2[off];
            Bl[j] = Wl2[off];
        }
        #pragma unroll
        for (int i = 0; i < 4; i++) {
            #pragma unroll
            for (int j = 0; j < 4; j++) {
                mma16816(acc[i][j], (const uint32_t*)&Ah[i], (const uint32_t*)&Bh[j]);
                mma16816(acc[i][j], (const uint32_t*)&Ah[i], (const uint32_t*)&Bl[j]);
                mma16816(acc[i][j], (const uint32_t*)&Al[i], (const uint32_t*)&Bh[j]);
            }
        }
    }

    int g = lane >> 2, tg = lane & 3;
    #pragma unroll
    for (int i = 0; i < 4; i++) {
        #pragma unroll
        for (int j = 0; j < 4; j++) {
            size_t row = (size_t)(mt0 + i)*16 + g;
            size_t col = (size_t)(nt0 + j)*8 + tg*2;
            *(float2*)(g_T + row*512 + col)       = make_float2(acc[i][j][0], acc[i][j][1]);
            *(float2*)(g_T + (row + 8)*512 + col) = make_float2(acc[i][j][2], acc[i][j][3]);
        }
    }
}

// ---------------- K-fuse2: z = T_top + ideg*gather(T_bot) + bias (raw) ---------
// grid (NB, 2 which, 2 fh); block 1024; smem 64KB (256 nodes x 64 feats)
// writes raw z into g_feat/g_assign and per-(which,fh) row sum-of-squares.
__global__ void __launch_bounds__(1024) k_fuse2(const float* __restrict__ bf,
                                                const float* __restrict__ bp) {
    extern __shared__ float ts[];   // 256 x 64
    int b = blockIdx.x, which = blockIdx.y, fh = blockIdx.z, t = threadIdx.x;
    int top_off = which*256 + fh*64, bot_off = which*256 + 128 + fh*64;
    for (int i4 = t; i4 < 256*16; i4 += 1024) {
        int node = i4 >> 4, f4 = i4 & 15;
        ((float4*)ts)[i4] = *(const float4*)(g_T + (size_t)(b*NPER + node)*512 + bot_off + f4*4);
    }
    __syncthreads();
    const unsigned long long* tsv = (const unsigned long long*)ts;  // node*32 + l
    int w = t >> 5, l = t & 31;
    const float* bias = which ? bp : bf;
    float2 bias2 = *(const float2*)(bias + fh*64 + l*2);
    float* zout = which ? g_assign : g_feat;

    for (int ii = 0; ii < 8; ii++) {
        int dst = w*8 + ii;
        int gi = b*NPER + dst;
        int nn = g_ecnt[gi]; if (nn > MAXE) nn = MAXE;
        float ideg = g_ideg[gi];
        const unsigned char* lst = &g_elist[(size_t)gi*MAXE];
        unsigned long long a0 = 0, a1 = 0, a2 = 0, a3 = 0;
        int j = 0;
        for (; j + 4 <= nn; j += 4) {
            uchar4 s4 = *(const uchar4*)(lst + j);
            a0 = add2(a0, tsv[s4.x*32 + l]);
            a1 = add2(a1, tsv[s4.y*32 + l]);
            a2 = add2(a2, tsv[s4.z*32 + l]);
            a3 = add2(a3, tsv[s4.w*32 + l]);
        }
        for (; j < nn; j++) a0 = add2(a0, tsv[lst[j]*32 + l]);
        a0 = add2(add2(a0, a1), add2(a2, a3));
        float s0, s1;
        unpack2(a0, s0, s1);

        float2 top = *(const float2*)(g_T + (size_t)gi*512 + top_off + l*2);
        float z0 = fmaf(ideg, s0, top.x) + bias2.x;
        float z1 = fmaf(ideg, s1, top.y) + bias2.y;

        *(float2*)(zout + (size_t)gi*DOUT + fh*64 + l*2) = make_float2(z0, z1);

        float ssq = z0*z0 + z1*z1;
        #pragma unroll
        for (int o = 16; o > 0; o >>= 1) ssq += __shfl_xor_sync(0xffffffffu, ssq, o);
        if (l == 0) g_ssq[(which*2 + fh)*NROWS + gi] = ssq;
    }
}

// ---------------- K-norm: normalize + relu (+softmax for pool) -----------------
// 1 warp per (which,row); block 256 = 8 warps; grid 4096.
// softmax: values in [0,1] after relu -> exp without max subtraction is exact math.
__global__ void __launch_bounds__(256) k_norm() {
    int wid = blockIdx.x*8 + (threadIdx.x >> 5);
    int l = threadIdx.x & 31;
    int which = wid >> 14;
    int gi = wid & (NROWS - 1);
    float* buf = which ? g_assign : g_feat;
    float4 z = *(const float4*)(buf + (size_t)gi*DOUT + l*4);
    float ssq = g_ssq[(which*2)*NROWS + gi] + g_ssq[(which*2 + 1)*NROWS + gi];
    float inv = rsqrtf(fmaxf(ssq, 1e-24f));
    float q0 = fmaxf(z.x*inv, 0.f), q1 = fmaxf(z.y*inv, 0.f);
    float q2 = fmaxf(z.z*inv, 0.f), q3 = fmaxf(z.w*inv, 0.f);
    if (which == 0) {
        *(float4*)(buf + (size_t)gi*DOUT + l*4) = make_float4(q0, q1, q2, q3);
    } else {
        float e0 = __expf(q0), e1 = __expf(q1), e2 = __expf(q2), e3 = __expf(q3);
        float s = (e0 + e1) + (e2 + e3);
        #pragma unroll
        for (int o = 16; o > 0; o >>= 1) s += __shfl_xor_sync(0xffffffffu, s, o);
        float isum = 1.0f / s;
        *(float4*)(buf + (size_t)gi*DOUT + l*4) =
            make_float4(e0*isum, e1*isum, e2*isum, e3*isum);
    }
}

// ---------------- K-as: AS = A @ assign ; feature/dst split ----------------
__global__ void __launch_bounds__(1024) k_as() {
    extern __shared__ float ss[];
    int b = blockIdx.x, fh = blockIdx.y, dh = blockIdx.z, t = threadIdx.x;
    for (int i4 = t; i4 < 256*16; i4 += 1024) {
        int node = i4 >> 4, f4 = i4 & 15;
        ((float4*)ss)[i4] = *(const float4*)(g_assign + (size_t)(b*NPER + node)*DOUT + fh*64 + f4*4);
    }
    __syncthreads();
    const unsigned long long* ssv = (const unsigned long long*)ss;
    int w = t >> 5, l = t & 31;
    for (int ii = 0; ii < 4; ii++) {
        int dst = dh*128 + w*4 + ii;
        int gi = b*NPER + dst;
        int nn = g_ecnt[gi]; if (nn > MAXE) nn = MAXE;
        const unsigned char* lst = &g_elist[(size_t)gi*MAXE];
        unsigned long long a0 = 0, a1 = 0, a2 = 0, a3 = 0;
        int j = 0;
        for (; j + 4 <= nn; j += 4) {
            uchar4 s4 = *(const uchar4*)(lst + j);
            a0 = add2(a0, ssv[s4.x*32 + l]);
            a1 = add2(a1, ssv[s4.y*32 + l]);
            a2 = add2(a2, ssv[s4.z*32 + l]);
            a3 = add2(a3, ssv[s4.w*32 + l]);
        }
        for (; j < nn; j++) a0 = add2(a0, ssv[lst[j]*32 + l]);
        a0 = add2(add2(a0, a1), add2(a2, a3));
        float lo, hi;
        unpack2(a0, lo, hi);
        *(float2*)(g_AS + (size_t)gi*DOUT + fh*64 + l*2) = make_float2(lo, hi);
    }
}

// ---------------- K-pool: out = S^T @ X ; 256 thr, 64KB smem, 2 blocks/SM ------
__global__ void __launch_bounds__(256) k_pool(float* __restrict__ out) {
    extern __shared__ float sm[];
    float* Ssm = sm;           // 64 x 128
    float* Xsm = sm + 8192;    // 64 x 128
    int b = blockIdx.x, which = blockIdx.y;
    int t = threadIdx.x;
    int tk = t >> 4, td = t & 15;

    const float* Sg = g_assign + (size_t)b*NPER*DOUT;
    const float* Xg = (which ? g_AS : g_feat) + (size_t)b*NPER*DOUT;

    unsigned long long acc[8][4];
    #pragma unroll
    for (int i = 0; i < 8; i++)
        #pragma unroll
        for (int j = 0; j < 4; j++) acc[i][j] = 0ull;

    for (int c = 0; c < NPER; c += 64) {
        const float4* Sg4 = (const float4*)(Sg + c*128);
        const float4* Xg4 = (const float4*)(Xg + c*128);
        for (int i4 = t; i4 < 64*32; i4 += 256) {
            ((float4*)Ssm)[i4] = Sg4[i4];
            ((float4*)Xsm)[i4] = Xg4[i4];
        }
        __syncthreads();
        for (int n = 0; n < 64; n++) {
            float4 a0 = ((const float4*)(Ssm + n*128))[tk*2];
            float4 a1 = ((const float4*)(Ssm + n*128))[tk*2 + 1];
            ulonglong2 x0 = ((const ulonglong2*)(Xsm + n*128))[td*2];
            ulonglong2 x1 = ((const ulonglong2*)(Xsm + n*128))[td*2 + 1];
            unsigned long long A[8] = {
                dup2(a0.x), dup2(a0.y), dup2(a0.z), dup2(a0.w),
                dup2(a1.x), dup2(a1.y), dup2(a1.z), dup2(a1.w)
            };
            #pragma unroll
            for (int i = 0; i < 8; i++) {
                acc[i][0] = fma2(x0.x, A[i], acc[i][0]);
                acc[i][1] = fma2(x0.y, A[i], acc[i][1]);
                acc[i][2] = fma2(x1.x, A[i], acc[i][2]);
                acc[i][3] = fma2(x1.y, A[i], acc[i][3]);
            }
        }
        __syncthreads();
    }

    #pragma unroll
    for (int i = 0; i < 8; i++) {
        size_t grow = (size_t)b*128 + tk*8 + i;
        size_t base = which ? (grow*ADJ_N + (size_t)b*128 + td*8)
                            : ((size_t)ADJ_ELEMS + grow*DOUT + td*8);
        #pragma unroll
        for (int j = 0; j < 4; j++) {
            float lo, hi;
            unpack2(acc[i][j], lo, hi);
            out[base + 2*j]     = lo;
            out[base + 2*j + 1] = hi;
        }
    }
}

// ---------------- launch ----------------
extern "C" void kernel_launch(void* const* d_in, const int* in_sizes, int n_in,
                              void* d_out, int out_size) {
    const float* h    = (const float*)d_in[0];
    const int*   esrc = (const int*)d_in[1];
    const int*   edst = (const int*)d_in[2];
    const float* Wf   = (const float*)d_in[3];
    const float* bf   = (const float*)d_in[4];
    const float* Wp   = (const float*)d_in[5];
    const float* bp   = (const float*)d_in[6];
    float* out = (float*)d_out;

    static cudaStream_t s_side = nullptr;
    static cudaEvent_t  e_fork = nullptr, e_build = nullptr, e_join = nullptr;
    static bool attr_done = false;
    if (!s_side) {
        cudaStreamCreateWithFlags(&s_side, cudaStreamNonBlocking);
        cudaEventCreateWithFlags(&e_fork,  cudaEventDisableTiming);
        cudaEventCreateWithFlags(&e_build, cudaEventDisableTiming);
        cudaEventCreateWithFlags(&e_join,  cudaEventDisableTiming);
    }
    if (!attr_done) {
        cudaFuncSetAttribute(k_fuse2, cudaFuncAttributeMaxDynamicSharedMemorySize, 65536);
        cudaFuncSetAttribute(k_as,    cudaFuncAttributeMaxDynamicSharedMemorySize, 65536);
        cudaFuncSetAttribute(k_pool,  cudaFuncAttributeMaxDynamicSharedMemorySize, 65536);
        attr_done = true;
    }

    // side stream: edge-list build, then adj memset (overlaps prep+gemm)
    cudaEventRecord(e_fork, 0);
    cudaStreamWaitEvent(s_side, e_fork, 0);
    k_build<<<NB, 256, 0, s_side>>>(esrc, edst);
    cudaEventRecord(e_build, s_side);
    cudaMemsetAsync(d_out, 0, (size_t)ADJ_ELEMS * sizeof(float), s_side);
    cudaEventRecord(e_join, s_side);

    // main stream
    k_prep<<<8448, 256>>>(h, Wf, Wp);
    k_gemm_mma<<<dim3(128, 4), 256>>>();
    cudaStreamWaitEvent(0, e_build, 0);
    k_fuse2<<<dim3(NB, 2, 2), 1024, 65536>>>(bf, bp);
    k_norm<<<4096, 256>>>();
    k_as<<<dim3(NB, 2, 2), 1024, 65536>>>();
    cudaStreamWaitEvent(0, e_join, 0);
    k_pool<<<dim3(NB, 2), 256, 65536>>>(out);
}

// round 9
// speedup vs baseline: 1.0476x; 1.0476x over previous
#include <cuda_runtime.h>
#include <cuda_bf16.h>
#include <math.h>
#include <stdint.h>

#define NB   64
#define NPER 256
#define DIN  256
#define DOUT 128
#define EPER 8192
#define MAXE 192
#define ADJ_N 8192
#define ADJ_ELEMS (67108864u)
#define NROWS (NB*NPER)          // 16384

// ---------------- scratch ----------------
__device__ float g_T[NROWS*512];                // X @ Wcat  (cols: Wf_top|Wf_bot|Wp_top|Wp_bot)
__device__ float g_feat[NROWS*DOUT];
__device__ float g_assign[NROWS*DOUT];
__device__ float g_AS[NROWS*DOUT];
__device__ unsigned char g_elist[NROWS*MAXE];
__device__ int   g_ecnt[NROWS];
__device__ float g_ideg[NROWS];
// fragment-major bf16x2 words:
//   X:  [m_tile(1024)][k_chunk(16)][lane(32)][reg(4)]
//   WT: [n_tile(64)]  [k_chunk(16)][lane(32)][reg(2)]
__device__ unsigned int g_Xh[NROWS*128];
__device__ unsigned int g_Xl[NROWS*128];
__device__ unsigned int g_WTh[512*128];
__device__ unsigned int g_WTl[512*128];

// ---------------- f32x2 helpers ----------------
__device__ __forceinline__ unsigned long long fma2(unsigned long long a,
                                                   unsigned long long b,
                                                   unsigned long long c) {
    unsigned long long d;
    asm("fma.rn.f32x2 %0, %1, %2, %3;" : "=l"(d) : "l"(a), "l"(b), "l"(c));
    return d;
}
__device__ __forceinline__ unsigned long long add2(unsigned long long a,
                                                   unsigned long long b) {
    unsigned long long d;
    asm("add.rn.f32x2 %0, %1, %2;" : "=l"(d) : "l"(a), "l"(b));
    return d;
}
__device__ __forceinline__ unsigned long long dup2(float w) {
    unsigned long long d;
    asm("mov.b64 %0, {%1, %1};" : "=l"(d) : "f"(w));
    return d;
}
__device__ __forceinline__ void unpack2(unsigned long long v, float& lo, float& hi) {
    asm("mov.b64 {%0, %1}, %2;" : "=f"(lo), "=f"(hi) : "l"(v));
}

// ---------------- mma.sync bf16 (baseline PTX) ----------
__device__ __forceinline__ void mma16816(float* c, const uint32_t* a, const uint32_t* b) {
    asm volatile(
        "mma.sync.aligned.m16n8k16.row.col.f32.bf16.bf16.f32 "
        "{%0,%1,%2,%3}, {%4,%5,%6,%7}, {%8,%9}, {%0,%1,%2,%3};"
        : "+f"(c[0]), "+f"(c[1]), "+f"(c[2]), "+f"(c[3])
        : "r"(a[0]), "r"(a[1]), "r"(a[2]), "r"(a[3]), "r"(b[0]), "r"(b[1]));
}

// ---------------- K-build ----------------
__global__ void k_build(const int* __restrict__ esrc, const int* __restrict__ edst) {
    int b = blockIdx.x;
    __shared__ int scnt[NPER];
    for (int i = threadIdx.x; i < NPER; i += blockDim.x) scnt[i] = 0;
    __syncthreads();
    const int* s = esrc + b*EPER;
    const int* d = edst + b*EPER;
    for (int e = threadIdx.x; e < EPER; e += blockDim.x) {
        int dst = d[e];
        int src = s[e];
        int pos = atomicAdd(&scnt[dst], 1);
        if (pos < MAXE) g_elist[(b*NPER + dst)*MAXE + pos] = (unsigned char)src;
    }
    __syncthreads();
    for (int i = threadIdx.x; i < NPER; i += blockDim.x) {
        int c = scnt[i];
        g_ecnt[b*NPER + i] = c;
        g_ideg[b*NPER + i] = 1.0f / (float)(c > 0 ? c : 1);
    }
}

// ---------------- K-prep: bf16 hi/lo split into mma-fragment layout ------------
__device__ __forceinline__ void split2(float a, float b, unsigned int& hi, unsigned int& lo) {
    __nv_bfloat16 ah = __float2bfloat16(a);
    __nv_bfloat16 bh = __float2bfloat16(b);
    __nv_bfloat16 al = __float2bfloat16(a - __bfloat162float(ah));
    __nv_bfloat16 bl = __float2bfloat16(b - __bfloat162float(bh));
    __nv_bfloat162 hh; hh.x = ah; hh.y = bh;
    __nv_bfloat162 ll; ll.x = al; ll.y = bl;
    hi = *reinterpret_cast<unsigned int*>(&hh);
    lo = *reinterpret_cast<unsigned int*>(&ll);
}

// blocks 0..1023: X m-tiles (smem-staged, coalesced in AND out)
// blocks 1024..1279: W fragments (tiny, scattered reads OK)
__global__ void __launch_bounds__(256) k_prep(
        const float* __restrict__ h,
        const float* __restrict__ Wf, const float* __restrict__ Wp) {
    __shared__ float hs[16*256];     // one m-tile: 16 rows x 256 cols (16KB)
    int t = threadIdx.x;
    if (blockIdx.x < 1024) {
        int mt = blockIdx.x;
        const float4* src = (const float4*)(h + (size_t)mt*16*DIN);
        // coalesced load: 1024 float4s
        #pragma unroll
        for (int k = 0; k < 4; k++)
            ((float4*)hs)[t + k*256] = src[t + k*256];
        __syncthreads();
        // each thread emits 8 fragment words, consecutive w -> coalesced stores
        #pragma unroll
        for (int k = 0; k < 8; k++) {
            int w = t + k*256;                   // [0,2048)
            int reg = w & 3, lane = (w >> 2) & 31, kc = w >> 7;
            int g = lane >> 2, tg = lane & 3;
            int row = g + (reg & 1)*8;
            int wc = tg + (reg >> 1)*4;
            const float* hp = hs + row*256 + (kc*8 + wc)*2;
            unsigned int hi, lo;
            split2(hp[0], hp[1], hi, lo);
            g_Xh[(size_t)mt*2048 + w] = hi;
            g_Xl[(size_t)mt*2048 + w] = lo;
        }
    } else {
        int widx = (blockIdx.x - 1024)*256 + t;   // [0, 65536)
        int reg = widx & 1, lane = (widx >> 1) & 31, kc = (widx >> 6) & 15, nt = widx >> 10;
        int g = lane >> 2, tg = lane & 3;
        int n = nt*8 + g;
        int w = tg + reg*4;
        int k = (kc*8 + w)*2;
        int seg = n >> 7;
        const float* Wb = (seg < 2) ? Wf : Wp;
        int col = n & 127;
        int krow = k + ((seg & 1) ? 256 : 0);
        float x0 = Wb[(size_t)krow*128 + col];
        float x1 = Wb[(size_t)(krow+1)*128 + col];
        unsigned int hi, lo;
        split2(x0, x1, hi, lo);
        g_WTh[widx] = hi;
        g_WTl[widx] = lo;
    }
}

// ---------------- K-gemm (HMMA): T = X @ Wcat via 3-pass bf16 split ------------
__global__ void __launch_bounds__(256) k_gemm_mma() {
    int t = threadIdx.x, lane = t & 31, w = t >> 5;
    int wm = w & 1, wn = w >> 1;
    int mt0 = blockIdx.x*8 + wm*4;      // m-tile (16 rows each)
    int nt0 = blockIdx.y*16 + wn*4;     // n-tile (8 cols each)

    float acc[4][4][4];
    #pragma unroll
    for (int i = 0; i < 4; i++)
        #pragma unroll
        for (int j = 0; j < 4; j++)
            #pragma unroll
            for (int r = 0; r < 4; r++) acc[i][j][r] = 0.f;

    const uint4* Xh4 = (const uint4*)g_Xh;
    const uint4* Xl4 = (const uint4*)g_Xl;
    const uint2* Wh2 = (const uint2*)g_WTh;
    const uint2* Wl2 = (const uint2*)g_WTl;

    for (int kc = 0; kc < 16; kc++) {
        uint4 Ah[4], Al[4];
        uint2 Bh[4], Bl[4];
        #pragma unroll
        for (int i = 0; i < 4; i++) {
            int off = ((mt0 + i)*16 + kc)*32 + lane;
            Ah[i] = Xh4[off];
            Al[i] = Xl4[off];
        }
        #pragma unroll
        for (int j = 0; j < 4; j++) {
            int off = ((nt0 + j)*16 + kc)*32 + lane;
            Bh[j] = Wh2[off];
            Bl[j] = Wl2[off];
        }
        #pragma unroll
        for (int i = 0; i < 4; i++) {
            #pragma unroll
            for (int j = 0; j < 4; j++) {
                mma16816(acc[i][j], (const uint32_t*)&Ah[i], (const uint32_t*)&Bh[j]);
                mma16816(acc[i][j], (const uint32_t*)&Ah[i], (const uint32_t*)&Bl[j]);
                mma16816(acc[i][j], (const uint32_t*)&Al[i], (const uint32_t*)&Bh[j]);
            }
        }
    }

    int g = lane >> 2, tg = lane & 3;
    #pragma unroll
    for (int i = 0; i < 4; i++) {
        #pragma unroll
        for (int j = 0; j < 4; j++) {
            size_t row = (size_t)(mt0 + i)*16 + g;
            size_t col = (size_t)(nt0 + j)*8 + tg*2;
            *(float2*)(g_T + row*512 + col)       = make_float2(acc[i][j][0], acc[i][j][1]);
            *(float2*)(g_T + (row + 8)*512 + col) = make_float2(acc[i][j][2], acc[i][j][3]);
        }
    }
}

// ---------------- K-fuse: Z = T_top + ideg*gather(T_bot) + bias, epilogue ------
// grid (NB, 2: which); block 1024; smem 128KB (full 128 feats)
__global__ void __launch_bounds__(1024) k_fuse(const float* __restrict__ bf,
                                               const float* __restrict__ bp) {
    extern __shared__ float ts[];
    int b = blockIdx.x, which = blockIdx.y, t = threadIdx.x;
    int top_off = which*256, bot_off = which*256 + 128;
    for (int i4 = t; i4 < 256*32; i4 += 1024) {
        int node = i4 >> 5, f4 = i4 & 31;
        ((float4*)ts)[i4] = *(const float4*)(g_T + (size_t)(b*NPER + node)*512 + bot_off + f4*4);
    }
    __syncthreads();
    const ulonglong2* tsv = (const ulonglong2*)ts;
    int w = t >> 5, l = t & 31;
    const float* bias = which ? bp : bf;
    float4 bias4 = *(const float4*)(bias + l*4);

    for (int ii = 0; ii < 8; ii++) {
        int dst = w*8 + ii;
        int gi = b*NPER + dst;
        int nn = g_ecnt[gi]; if (nn > MAXE) nn = MAXE;
        float ideg = g_ideg[gi];
        const unsigned char* lst = &g_elist[(size_t)gi*MAXE];
        unsigned long long a0 = 0, a1 = 0, b0 = 0, b1 = 0;
        int j = 0;
        for (; j + 4 <= nn; j += 4) {
            uchar4 s4 = *(const uchar4*)(lst + j);
            ulonglong2 v0 = tsv[s4.x*32 + l];
            ulonglong2 v1 = tsv[s4.y*32 + l];
            ulonglong2 v2 = tsv[s4.z*32 + l];
            ulonglong2 v3 = tsv[s4.w*32 + l];
            a0 = add2(a0, v0.x); a1 = add2(a1, v0.y);
            b0 = add2(b0, v1.x); b1 = add2(b1, v1.y);
            a0 = add2(a0, v2.x); a1 = add2(a1, v2.y);
            b0 = add2(b0, v3.x); b1 = add2(b1, v3.y);
        }
        for (; j < nn; j++) {
            ulonglong2 v = tsv[lst[j]*32 + l];
            a0 = add2(a0, v.x); a1 = add2(a1, v.y);
        }
        a0 = add2(a0, b0); a1 = add2(a1, b1);
        float s0, s1, s2, s3;
        unpack2(a0, s0, s1); unpack2(a1, s2, s3);

        float4 top = *(const float4*)(g_T + (size_t)gi*512 + top_off + l*4);
        float z0 = fmaf(ideg, s0, top.x) + bias4.x;
        float z1 = fmaf(ideg, s1, top.y) + bias4.y;
        float z2 = fmaf(ideg, s2, top.z) + bias4.z;
        float z3 = fmaf(ideg, s3, top.w) + bias4.w;

        float ss = z0*z0 + z1*z1 + z2*z2 + z3*z3;
        #pragma unroll
        for (int o = 16; o > 0; o >>= 1) ss += __shfl_xor_sync(0xffffffffu, ss, o);
        float inv = rsqrtf(fmaxf(ss, 1e-24f));
        z0 = fmaxf(z0*inv, 0.f); z1 = fmaxf(z1*inv, 0.f);
        z2 = fmaxf(z2*inv, 0.f); z3 = fmaxf(z3*inv, 0.f);

        if (which == 0) {
            *(float4*)(g_feat + (size_t)gi*DOUT + l*4) = make_float4(z0, z1, z2, z3);
        } else {
            float m = fmaxf(fmaxf(z0, z1), fmaxf(z2, z3));
            #pragma unroll
            for (int o = 16; o > 0; o >>= 1) m = fmaxf(m, __shfl_xor_sync(0xffffffffu, m, o));
            float e0 = __expf(z0 - m), e1 = __expf(z1 - m);
            float e2 = __expf(z2 - m), e3 = __expf(z3 - m);
            float s = e0 + e1 + e2 + e3;
            #pragma unroll
            for (int o = 16; o > 0; o >>= 1) s += __shfl_xor_sync(0xffffffffu, s, o);
            float isum = 1.0f / s;
            *(float4*)(g_assign + (size_t)gi*DOUT + l*4) =
                make_float4(e0*isum, e1*isum, e2*isum, e3*isum);
        }
    }
}

// ---------------- K-as: AS[dst,:] = sum of assign[src,:] over in-edges --------
// grid (NB, 2 dst-halves); block 1024; smem 128KB (whole assign graph, LDS.128/edge)
__global__ void __launch_bounds__(1024) k_as() {
    extern __shared__ float ss[];
    int b = blockIdx.x, dh = blockIdx.y, t = threadIdx.x;
    const float4* Sg4 = (const float4*)(g_assign + (size_t)b*NPER*DOUT);
    for (int i4 = t; i4 < 256*32; i4 += 1024) ((float4*)ss)[i4] = Sg4[i4];
    __syncthreads();
    const ulonglong2* ssv = (const ulonglong2*)ss;
    int w = t >> 5, l = t & 31;
    for (int ii = 0; ii < 4; ii++) {
        int dst = dh*128 + w*4 + ii;
        int gi = b*NPER + dst;
        int nn = g_ecnt[gi]; if (nn > MAXE) nn = MAXE;
        const unsigned char* lst = &g_elist[(size_t)gi*MAXE];
        unsigned long long a0 = 0, a1 = 0, b0 = 0, b1 = 0;
        int j = 0;
        for (; j + 4 <= nn; j += 4) {
            uchar4 s4 = *(const uchar4*)(lst + j);
            ulonglong2 v0 = ssv[s4.x*32 + l];
            ulonglong2 v1 = ssv[s4.y*32 + l];
            ulonglong2 v2 = ssv[s4.z*32 + l];
            ulonglong2 v3 = ssv[s4.w*32 + l];
            a0 = add2(a0, v0.x); a1 = add2(a1, v0.y);
            b0 = add2(b0, v1.x); b1 = add2(b1, v1.y);
            a0 = add2(a0, v2.x); a1 = add2(a1, v2.y);
            b0 = add2(b0, v3.x); b1 = add2(b1, v3.y);
        }
        for (; j < nn; j++) {
            ulonglong2 v = ssv[lst[j]*32 + l];
            a0 = add2(a0, v.x); a1 = add2(a1, v.y);
        }
        a0 = add2(a0, b0); a1 = add2(a1, b1);
        float x0, x1, x2, x3;
        unpack2(a0, x0, x1); unpack2(a1, x2, x3);
        *(float4*)(g_AS + (size_t)gi*DOUT + l*4) = make_float4(x0, x1, x2, x3);
    }
}

// ---------------- K-pool: out = S^T @ X (which=0 h_pool, which=1 adj blocks) ---
__global__ void __launch_bounds__(512) k_pool(float* __restrict__ out) {
    extern __shared__ float sm[];
    int b = blockIdx.x, which = blockIdx.y;
    int t = threadIdx.x;
    int team = t >> 8;
    int tt = t & 255;
    int tk = tt >> 4, td = tt & 15;

    float* Ssm = sm + team*16384;
    float* Xsm = sm + team*16384 + 8192;

    const float* Sg = g_assign + (size_t)b*NPER*DOUT;
    const float* Xg = (which ? g_AS : g_feat) + (size_t)b*NPER*DOUT;

    unsigned long long acc[8][4];
    #pragma unroll
    for (int i = 0; i < 8; i++)
        #pragma unroll
        for (int j = 0; j < 4; j++) acc[i][j] = 0ull;

    for (int ci = 0; ci < 2; ci++) {
        int c = team*128 + ci*64;
        const float4* Sg4 = (const float4*)(Sg + c*128);
        const float4* Xg4 = (const float4*)(Xg + c*128);
        for (int i4 = tt; i4 < 64*32; i4 += 256) {
            ((float4*)Ssm)[i4] = Sg4[i4];
            ((float4*)Xsm)[i4] = Xg4[i4];
        }
        __syncthreads();
        for (int n = 0; n < 64; n++) {
            float4 a0 = ((const float4*)(Ssm + n*128))[tk*2];
            float4 a1 = ((const float4*)(Ssm + n*128))[tk*2 + 1];
            ulonglong2 x0 = ((const ulonglong2*)(Xsm + n*128))[td*2];
            ulonglong2 x1 = ((const ulonglong2*)(Xsm + n*128))[td*2 + 1];
            unsigned long long A[8] = {
                dup2(a0.x), dup2(a0.y), dup2(a0.z), dup2(a0.w),
                dup2(a1.x), dup2(a1.y), dup2(a1.z), dup2(a1.w)
            };
            #pragma unroll
            for (int i = 0; i < 8; i++) {
                acc[i][0] = fma2(x0.x, A[i], acc[i][0]);
                acc[i][1] = fma2(x0.y, A[i], acc[i][1]);
                acc[i][2] = fma2(x1.x, A[i], acc[i][2]);
                acc[i][3] = fma2(x1.y, A[i], acc[i][3]);
            }
        }
        __syncthreads();
    }

    float* cb = sm + 16384;
    if (team == 1) {
        #pragma unroll
        for (int i = 0; i < 8; i++) {
            float* row = cb + (tk*8 + i)*128 + td*8;
            #pragma unroll
            for (int j = 0; j < 4; j++) {
                float lo, hi;
                unpack2(acc[i][j], lo, hi);
                row[2*j] = lo; row[2*j + 1] = hi;
            }
        }
    }
    __syncthreads();
    if (team == 0) {
        #pragma unroll
        for (int i = 0; i < 8; i++) {
            const float* row = cb + (tk*8 + i)*128 + td*8;
            size_t grow = (size_t)b*128 + tk*8 + i;
            size_t base = which ? (grow*ADJ_N + (size_t)b*128 + td*8)
                                : ((size_t)ADJ_ELEMS + grow*DOUT + td*8);
            #pragma unroll
            for (int j = 0; j < 4; j++) {
                float lo, hi;
                unpack2(acc[i][j], lo, hi);
                out[base + 2*j]     = lo + row[2*j];
                out[base + 2*j + 1] = hi + row[2*j + 1];
            }
        }
    }
}

// ---------------- launch ----------------
extern "C" void kernel_launch(void* const* d_in, const int* in_sizes, int n_in,
                              void* d_out, int out_size) {
    const float* h    = (const float*)d_in[0];
    const int*   esrc = (const int*)d_in[1];
    const int*   edst = (const int*)d_in[2];
    const float* Wf   = (const float*)d_in[3];
    const float* bf   = (const float*)d_in[4];
    const float* Wp   = (const float*)d_in[5];
    const float* bp   = (const float*)d_in[6];
    float* out = (float*)d_out;

    static cudaStream_t s_side = nullptr;
    static cudaEvent_t  e_fork = nullptr, e_build = nullptr, e_join = nullptr;
    static bool attr_done = false;
    if (!s_side) {
        cudaStreamCreateWithFlags(&s_side, cudaStreamNonBlocking);
        cudaEventCreateWithFlags(&e_fork,  cudaEventDisableTiming);
        cudaEventCreateWithFlags(&e_build, cudaEventDisableTiming);
        cudaEventCreateWithFlags(&e_join,  cudaEventDisableTiming);
    }
    if (!attr_done) {
        cudaFuncSetAttribute(k_fuse, cudaFuncAttributeMaxDynamicSharedMemorySize, 131072);
        cudaFuncSetAttribute(k_as,   cudaFuncAttributeMaxDynamicSharedMemorySize, 131072);
        cudaFuncSetAttribute(k_pool, cudaFuncAttributeMaxDynamicSharedMemorySize, 131072);
        attr_done = true;
    }

    // side stream: edge-list build, then adj memset (overlaps prep+gemm)
    cudaEventRecord(e_fork, 0);
    cudaStreamWaitEvent(s_side, e_fork, 0);
    k_build<<<NB, 256, 0, s_side>>>(esrc, edst);
    cudaEventRecord(e_build, s_side);
    cudaMemsetAsync(d_out, 0, (size_t)ADJ_ELEMS * sizeof(float), s_side);
    cudaEventRecord(e_join, s_side);

    // main stream
    k_prep<<<1280, 256>>>(h, Wf, Wp);
    k_gemm_mma<<<dim3(128, 4), 256>>>();
    cudaStreamWaitEvent(0, e_build, 0);
    k_fuse<<<dim3(NB, 2), 1024, 131072>>>(bf, bp);
    k_as<<<dim3(NB, 2), 1024, 131072>>>();
    cudaStreamWaitEvent(0, e_join, 0);
    k_pool<<<dim3(NB, 2), 512, 131072>>>(out);
}